// round 7
// baseline (speedup 1.0000x reference)
#include <cuda_runtime.h>
#include <cuda_fp16.h>
#include <cstdint>

// B=256, T=64 (K), S=16, U=4 -> P=256 pixels, O=1024 outputs/pixel.
//
// Legacy mma.sync on sm_103a is hard-walled at 64 MAC/cyc/SM (measured, invariant
// across tf32/fp16/occupancy). The fma pipe is idle. Hybrid:
//   tensor path (bn 0..4,  o <320): R6 fp16 m16n8k16 kernel, 64 MAC/cyc/SM
//   FFMA2 path  (bn 5..15, o>=320): packed fp32 fma.rn.f32x2, ~128 MAC/cyc/SM
// Both in one grid; co-resident CTAs drive both pipes concurrently.
//
// kernel A: transpose+permute x -> g_xA (fp16, m16n8k16 A-fragment order)
// kernel B: transpose x -> g_xT32[p][t][b] (fp32, t-major for FFMA2 path)
// kernel C: hybrid GEMM, epilogue scatters into pixel-shuffle layout.

__device__ uint32_t g_xA[256 * 8192];        // fp16 frag order, 8 MB
__device__ float    g_xT32[256 * 64 * 256];  // [p][t][b] fp32, 16 MB

__device__ __forceinline__ uint32_t smem_u32(const void* p) {
    uint32_t a;
    asm("{ .reg .u64 t; cvta.to.shared.u64 t, %1; cvt.u32.u64 %0, t; }" : "=r"(a) : "l"(p));
    return a;
}
__device__ __forceinline__ void cp16(uint32_t sdst, const void* g) {
    asm volatile("cp.async.cg.shared.global [%0], [%1], 16;" :: "r"(sdst), "l"(g));
}
__device__ __forceinline__ unsigned long long packf2(float lo, float hi) {
    unsigned long long v;
    asm("mov.b64 %0, {%1, %2};" : "=l"(v) : "f"(lo), "f"(hi));
    return v;
}
__device__ __forceinline__ float2 unpackf2(unsigned long long v) {
    float2 r;
    asm("mov.b64 {%0, %1}, %2;" : "=f"(r.x), "=f"(r.y) : "l"(v));
    return r;
}

// m16n8k16 A-fragment offset (uint32 units) for element pair (b, t even).
__device__ __forceinline__ int a_off_u32(int b, int t) {
    int g = b & 7, hi8 = (b >> 3) & 1;
    int pr = (t & 15) >> 1;
    int tig = pr & 3, reg = hi8 + ((pr >> 2) << 1);
    return ((b >> 4) << 9) + ((t >> 4) << 7) + ((g * 4 + tig) << 2) + reg;
}

// ---------------------------------------------------------------------------
// Transpose A (fp16 fragment order): x[b][t][p] -> g_xA
// ---------------------------------------------------------------------------
__global__ void transpose_kernel(const float* __restrict__ x) {
    __shared__ float tile[32][33];
    int p0 = blockIdx.x * 32, t0 = blockIdx.y * 32, b = blockIdx.z;
    int tx = threadIdx.x, ty = threadIdx.y;
    int tid = ty * 32 + tx;
    const float* src = x + (size_t)b * 16384 + (size_t)t0 * 256 + p0;
#pragma unroll
    for (int k = 0; k < 4; k++) {
        int t = ty + k * 8;
        tile[t][tx] = src[t * 256 + tx];
    }
    __syncthreads();
#pragma unroll
    for (int k = 0; k < 2; k++) {
        int idx = tid + k * 256;
        int pl = idx >> 4;
        int j  = idx & 15;
        int p = p0 + pl;
        int t = t0 + 2 * j;
        __half2 h = __floats2half2_rn(tile[2 * j][pl], tile[2 * j + 1][pl]);
        g_xA[(size_t)p * 8192 + a_off_u32(b, t)] = *(const uint32_t*)&h;
    }
}

// ---------------------------------------------------------------------------
// Transpose B (fp32 t-major): x[b][t][p] -> g_xT32[p*16384 + t*256 + b]
// grid (8 p-tiles, 8 b-tiles, 64 t), block (32, 8)
// ---------------------------------------------------------------------------
__global__ void transpose32_kernel(const float* __restrict__ x) {
    __shared__ float tile[32][33];
    int p0 = blockIdx.x * 32, b0 = blockIdx.y * 32, t = blockIdx.z;
    int tx = threadIdx.x, ty = threadIdx.y;
#pragma unroll
    for (int k = 0; k < 4; k++) {
        int br = ty + k * 8;
        tile[br][tx] = x[(size_t)(b0 + br) * 16384 + (size_t)t * 256 + p0 + tx];
    }
    __syncthreads();
#pragma unroll
    for (int k = 0; k < 4; k++) {
        int pr = ty + k * 8;
        g_xT32[(size_t)(p0 + pr) * 16384 + (size_t)t * 256 + b0 + tx] = tile[tx][pr];
    }
}

// ---------------------------------------------------------------------------
// Hybrid GEMM. grid (16, 2, 256). bn<5 -> tensor path, bn>=5 -> FFMA2 path.
// Both: C[128(b) x 64(o)] per CTA, o base = bn*64.
// ---------------------------------------------------------------------------
#define T_AS_U32 4096
#define T_WS_U32 2048
#define F_AS_F   (64 * 132)     // As[t][b], stride 132
#define F_WP_F   (32 * 128)     // Wp[kpair][o][2]
#define SMEM_BYTES ((F_AS_F + F_WP_F + 64) * 4)   // 50688 >= tensor需要 24832

__global__ __launch_bounds__(256, 2) void gemm_kernel(const float* __restrict__ Wg_all,
                                                      const float* __restrict__ bias,
                                                      float* __restrict__ out) {
    extern __shared__ char smem_raw[];
    const int bn = blockIdx.x;   // 0..15
    const int bm = blockIdx.y;   // 0..1
    const int p  = blockIdx.z;
    const int tid = threadIdx.x;
    const int i4 = (p >> 4) << 2, j4 = (p & 15) << 2;
    const float* Wg = Wg_all + ((size_t)p << 16) + (size_t)(bn * 64) * 64;
    const float* bias_g = bias + (size_t)p * 1024 + bn * 64;

    if (bn < 5) {
        // ================= tensor path (fp16 m16n8k16), o in [bn*64, bn*64+64) ====
        uint32_t* As = (uint32_t*)smem_raw;           // [8][4][32][4]
        uint32_t* Ws = As + T_AS_U32;                 // [8][4][32][2]
        float* bias_s = (float*)(Ws + T_WS_U32);      // [64]

        const int lane = tid & 31, warp = tid >> 5;
        const int wm = warp >> 1, wn = warp & 1;
        const int qr = lane >> 2, qc = lane & 3;

        const uint32_t* Ag = g_xA + ((size_t)p << 13) + (bm << 12);
        uint32_t sA = smem_u32(As);
#pragma unroll
        for (int i = 0; i < 4; i++) {
            int idx = tid + i * 256;
            cp16(sA + idx * 16, Ag + idx * 4);
        }
        if (tid < 16) cp16(smem_u32(bias_s) + tid * 16, bias_g + tid * 4);
        asm volatile("cp.async.commit_group;");

#pragma unroll
        for (int i = 0; i < 4; i++) {
            int idx = tid + i * 256;
            int r = idx >> 4;
            int c = (idx & 15) << 2;
            float4 v = *(const float4*)(Wg + r * 64 + c);
            int g = r & 7;
            int pA = (c & 15) >> 1;
            int reg = pA >> 2;
            int base = ((r >> 3) << 8) + ((c >> 4) << 6) + reg;
            __half2 h0 = __floats2half2_rn(v.x, v.y);
            __half2 h1 = __floats2half2_rn(v.z, v.w);
            Ws[base + ((g * 4 + (pA & 3)) << 1)]       = *(const uint32_t*)&h0;
            Ws[base + ((g * 4 + ((pA + 1) & 3)) << 1)] = *(const uint32_t*)&h1;
        }
        asm volatile("cp.async.wait_group 0;");
        __syncthreads();

        float acc[2][4][4];
#pragma unroll
        for (int mi = 0; mi < 2; mi++)
#pragma unroll
            for (int ni = 0; ni < 4; ni++)
#pragma unroll
                for (int q = 0; q < 4; q++) acc[mi][ni][q] = 0.f;

        const uint32_t* Abase = As + ((wm * 2) << 9) + lane * 4;
        const uint32_t* Bbase = Ws + ((wn * 4) << 8) + lane * 2;

#pragma unroll
        for (int ks = 0; ks < 4; ks++) {
            uint4 a[2];
            uint2 b[4];
#pragma unroll
            for (int mi = 0; mi < 2; mi++)
                a[mi] = *(const uint4*)(Abase + (mi << 9) + (ks << 7));
#pragma unroll
            for (int ni = 0; ni < 4; ni++)
                b[ni] = *(const uint2*)(Bbase + (ni << 8) + (ks << 6));
#pragma unroll
            for (int mi = 0; mi < 2; mi++)
#pragma unroll
                for (int ni = 0; ni < 4; ni++) {
                    asm("mma.sync.aligned.m16n8k16.row.col.f32.f16.f16.f32 "
                        "{%0,%1,%2,%3}, {%4,%5,%6,%7}, {%8,%9}, {%0,%1,%2,%3};"
                        : "+f"(acc[mi][ni][0]), "+f"(acc[mi][ni][1]),
                          "+f"(acc[mi][ni][2]), "+f"(acc[mi][ni][3])
                        : "r"(a[mi].x), "r"(a[mi].y), "r"(a[mi].z), "r"(a[mi].w),
                          "r"(b[ni].x), "r"(b[ni].y));
                }
        }

#pragma unroll
        for (int ni = 0; ni < 4; ni++) {
            int o_loc = wn * 32 + ni * 8 + 2 * qc;
            int o = bn * 64 + o_loc;
            int t  = o >> 4;
            int ui = (o >> 2) & 3;
            int uj = o & 3;
            int coloff = t * 4096 + (i4 + ui) * 64 + j4 + uj;
            float b0 = bias_s[o_loc];
            float b1 = bias_s[o_loc + 1];
#pragma unroll
            for (int mi = 0; mi < 2; mi++) {
                int row = bm * 128 + wm * 32 + mi * 16 + qr;
                *(float2*)(out + (size_t)row * 262144 + coloff) =
                    make_float2(acc[mi][ni][0] + b0, acc[mi][ni][1] + b1);
                *(float2*)(out + (size_t)(row + 8) * 262144 + coloff) =
                    make_float2(acc[mi][ni][2] + b0, acc[mi][ni][3] + b1);
            }
        }
    } else {
        // ================= FFMA2 path (packed fp32), o in [bn*64, bn*64+64) ======
        float* As = (float*)smem_raw;             // [64][132]
        float* Wp = As + F_AS_F;                  // [32 kpairs][64 o][2]
        float* bias_s = Wp + F_WP_F;              // [64]

        const int tb = tid & 15;                  // rows tb*8 .. tb*8+7
        const int to = tid >> 4;                  // cols to*4 .. to*4+3

        // A: g_xT32[p][t][bm*128 + 0..127] -> As[t][0..127] (stride 132)
        uint32_t sA = smem_u32(As);
        const float* Ag = g_xT32 + ((size_t)p << 14) + bm * 128;
#pragma unroll
        for (int i = 0; i < 8; i++) {
            int idx = tid + i * 256;          // 2048 chunks of 16B
            int t = idx >> 5;
            int c = (idx & 31) << 2;
            cp16(sA + (t * 132 + c) * 4, Ag + (size_t)t * 256 + c);
        }
        if (tid < 16) cp16(smem_u32(bias_s) + tid * 16, bias_g + tid * 4);
        asm volatile("cp.async.commit_group;");

        // W -> Wp[kpair][o][2]
#pragma unroll
        for (int i = 0; i < 4; i++) {
            int idx = tid + i * 256;          // 1024 float4s
            int o = idx & 63;
            int c = (idx >> 6) << 2;          // t, %4==0
            float4 v = *(const float4*)(Wg + o * 64 + c);
            float* dst = Wp + ((c >> 1) << 7) + o * 2;    // kpair = c/2
            *(float2*)dst          = make_float2(v.x, v.y);
            *(float2*)(dst + 128)  = make_float2(v.z, v.w);  // kpair+1
        }
        asm volatile("cp.async.wait_group 0;");
        __syncthreads();

        unsigned long long acc2[8][4];
        const unsigned long long z = packf2(0.f, 0.f);
#pragma unroll
        for (int i = 0; i < 8; i++)
#pragma unroll
            for (int j = 0; j < 4; j++) acc2[i][j] = z;

        const float* Acol = As + tb * 8;
        const unsigned long long* Bb = (const unsigned long long*)Wp + to * 4;

#pragma unroll 4
        for (int kp = 0; kp < 32; kp++) {
            const float* r0 = Acol + (2 * kp) * 132;
            float4 p0 = *(const float4*)r0;
            float4 p1 = *(const float4*)(r0 + 4);
            float4 q0 = *(const float4*)(r0 + 132);
            float4 q1 = *(const float4*)(r0 + 136);
            unsigned long long a2[8];
            a2[0] = packf2(p0.x, q0.x); a2[1] = packf2(p0.y, q0.y);
            a2[2] = packf2(p0.z, q0.z); a2[3] = packf2(p0.w, q0.w);
            a2[4] = packf2(p1.x, q1.x); a2[5] = packf2(p1.y, q1.y);
            a2[6] = packf2(p1.z, q1.z); a2[7] = packf2(p1.w, q1.w);
            ulonglong2 bb0 = *(const ulonglong2*)(Bb + (size_t)kp * 64);
            ulonglong2 bb1 = *(const ulonglong2*)(Bb + (size_t)kp * 64 + 2);
            unsigned long long b2[4] = {bb0.x, bb0.y, bb1.x, bb1.y};
#pragma unroll
            for (int i = 0; i < 8; i++)
#pragma unroll
                for (int j = 0; j < 4; j++) {
                    asm("fma.rn.f32x2 %0, %1, %2, %0;"
                        : "+l"(acc2[i][j]) : "l"(a2[i]), "l"(b2[j]));
                }
        }

        // Epilogue: thread's 4 o's are consecutive (uj 0..3) -> one STG.128 per row
        int o0 = bn * 64 + to * 4;
        int t  = o0 >> 4;
        int ui = (o0 >> 2) & 3;
        int coloff = t * 4096 + (i4 + ui) * 64 + j4;
        float4 bv = *(const float4*)&bias_s[to * 4];
#pragma unroll
        for (int i = 0; i < 8; i++) {
            int row = bm * 128 + tb * 8 + i;
            float2 c0 = unpackf2(acc2[i][0]);
            float2 c1 = unpackf2(acc2[i][1]);
            float2 c2 = unpackf2(acc2[i][2]);
            float2 c3 = unpackf2(acc2[i][3]);
            float4 v = make_float4(c0.x + c0.y + bv.x, c1.x + c1.y + bv.y,
                                   c2.x + c2.y + bv.z, c3.x + c3.y + bv.w);
            *(float4*)(out + (size_t)row * 262144 + coloff) = v;
        }
    }
}

extern "C" void kernel_launch(void* const* d_in, const int* in_sizes, int n_in,
                              void* d_out, int out_size) {
    const float* x = (const float*)d_in[0];   // (256, 64, 16, 16)
    const float* W = (const float*)d_in[1];   // (256, 1024, 64)
    const float* b = (const float*)d_in[2];   // (256, 1024)
    float* out = (float*)d_out;               // (256, 64, 64, 64)
    (void)in_sizes; (void)n_in; (void)out_size;

    cudaFuncSetAttribute(gemm_kernel, cudaFuncAttributeMaxDynamicSharedMemorySize, SMEM_BYTES);

    transpose_kernel<<<dim3(8, 2, 256), dim3(32, 8)>>>(x);
    transpose32_kernel<<<dim3(8, 8, 64), dim3(32, 8)>>>(x);
    gemm_kernel<<<dim3(16, 2, 256), 256, SMEM_BYTES>>>(W, b, out);
}

// round 9
// speedup vs baseline: 1.1840x; 1.1840x over previous
#include <cuda_runtime.h>
#include <cstdint>

// B=256, T=64 (K), S=16, U=4 -> P=256 pixels, O=1024 outputs/pixel.
//
// Finding: on the compute_103 toolchain target, mma.sync is EMULATED on the fma
// pipe at 64 MAC/cyc/SM (exact match across tf32/fp16/occupancy rounds). The
// fastest math path is packed-fp32 FFMA2 (fma.rn.f32x2, 128 MAC/cyc/SM).
// Pure FFMA2 kernel; k-pairs pre-packed in memory so the inner loop is
// LDS.128 + FFMA2 only.   (R8 -> R9: WROW 65 -> 66 fixes 16B misalignment.)
//
// kernel 1: transpose x (B,T,S,S) -> g_xP[p][kp][b] float2 = (x[2kp], x[2kp+1])
// kernel 2: CTA = (bn 16, bm 2, p 256): C[128 b x 64 o] = A @ W^T + bias.
//           A smem [32 kp][128 b] f32x2, W smem [32 kp][66] f32x2 (padded),
//           thread tile 8b x 4o, 32 f32x2 accumulators, horizontal add at end.
//           Epilogue: one STG.128 per row into pixel-shuffle layout.

__device__ float2 g_xP[256 * 8192];  // [p][kp 32][b 256], 16 MB

__device__ __forceinline__ uint32_t smem_u32(const void* p) {
    uint32_t a;
    asm("{ .reg .u64 t; cvta.to.shared.u64 t, %1; cvt.u32.u64 %0, t; }" : "=r"(a) : "l"(p));
    return a;
}
__device__ __forceinline__ void cp16(uint32_t sdst, const void* g) {
    asm volatile("cp.async.cg.shared.global [%0], [%1], 16;" :: "r"(sdst), "l"(g));
}
__device__ __forceinline__ float2 unpackf2(unsigned long long v) {
    float2 r;
    asm("mov.b64 {%0, %1}, %2;" : "=f"(r.x), "=f"(r.y) : "l"(v));
    return r;
}

// ---------------------------------------------------------------------------
// Transpose + k-pair pack: x[b][t][p] -> g_xP[p*8192 + kp*256 + b]
// grid (8 p-tiles, 8 b-tiles, 4 t-chunks), block (32, 8)
// ---------------------------------------------------------------------------
__global__ void transpose_pair(const float* __restrict__ x) {
    __shared__ float tl[2][32][33];   // [t-parity][b][p]
    int p0 = blockIdx.x * 32, b0 = blockIdx.y * 32, tc0 = blockIdx.z * 8;
    int tx = threadIdx.x, ty = threadIdx.y;
#pragma unroll 1
    for (int tp = 0; tp < 8; tp++) {
        int t = (tc0 + tp) * 2;
#pragma unroll
        for (int e = 0; e < 2; e++)
#pragma unroll
            for (int k = 0; k < 4; k++) {
                int bi = ty + k * 8;
                tl[e][bi][tx] = x[(size_t)(b0 + bi) * 16384 + (size_t)(t + e) * 256 + p0 + tx];
            }
        __syncthreads();
#pragma unroll
        for (int k = 0; k < 4; k++) {
            int pi = ty + k * 8;
            float2 v = make_float2(tl[0][tx][pi], tl[1][tx][pi]);   // b = b0+tx
            g_xP[(size_t)(p0 + pi) * 8192 + (size_t)(tc0 + tp) * 256 + b0 + tx] = v;
        }
        __syncthreads();
    }
}

// ---------------------------------------------------------------------------
// FFMA2 GEMM: C[128 b x 64 o] per CTA. 256 threads: to = tid&15 (o quad),
// tb = tid>>4 (b octet). 16 lanes share each A address (broadcast LDS).
// ---------------------------------------------------------------------------
#define WROW 66                         // Wp2 row stride in float2 (EVEN: 16B align)
#define AS_F2 (32 * 128)                // 32 KB
#define WS_F2 (32 * WROW)               // 16.5 KB
#define SMEM_BYTES ((AS_F2 + WS_F2) * 8 + 64 * 4)

__global__ __launch_bounds__(256) void gemm_kernel(const float* __restrict__ Wg_all,
                                                   const float* __restrict__ bias,
                                                   float* __restrict__ out) {
    extern __shared__ float2 smem2[];
    float2* As2 = smem2;                 // [32 kp][128 b]
    float2* Wp2 = smem2 + AS_F2;         // [32 kp][WROW]
    float* bias_s = (float*)(smem2 + AS_F2 + WS_F2);   // [64]

    const int bn = blockIdx.x;   // 0..15
    const int bm = blockIdx.y;   // 0..1
    const int p  = blockIdx.z;
    const int tid = threadIdx.x;
    const int to = tid & 15;     // o quad: o = bn*64 + to*4 .. +3
    const int tb = tid >> 4;     // b octet: b = bm*128 + tb*8 .. +7

    // A: 32 kp x 128 b float2 = 2048 16B chunks, cp.async
    const float2* Ag = g_xP + (size_t)p * 8192 + bm * 128;
    uint32_t sA = smem_u32(As2);
#pragma unroll
    for (int i = 0; i < 8; i++) {
        int idx = tid + i * 256;
        int kp = idx >> 6;
        int c2 = (idx & 63) * 2;           // float2 offset within row
        cp16(sA + (kp * 128 + c2) * 8, Ag + (size_t)kp * 256 + c2);
    }
    if (tid < 16) cp16(smem_u32(bias_s) + tid * 16, bias + (size_t)p * 1024 + bn * 64 + tid * 4);
    asm volatile("cp.async.commit_group;");

    // W: 64 o x 64 k -> Wp2[kp][o] = (W[o][2kp], W[o][2kp+1]); padded rows
    const float* Wg = Wg_all + ((size_t)p << 16) + (size_t)(bn * 64) * 64;
#pragma unroll
    for (int i = 0; i < 4; i++) {
        int idx = tid + i * 256;          // 1024 float4s
        int o = idx >> 4;                 // 0..63
        int kc = (idx & 15) << 2;         // 0..60
        float4 v = *(const float4*)(Wg + o * 64 + kc);
        int kp = kc >> 1;                 // even
        Wp2[kp * WROW + o]       = make_float2(v.x, v.y);
        Wp2[(kp + 1) * WROW + o] = make_float2(v.z, v.w);
    }
    asm volatile("cp.async.wait_group 0;");
    __syncthreads();

    unsigned long long acc2[8][4];
#pragma unroll
    for (int i = 0; i < 8; i++)
#pragma unroll
        for (int j = 0; j < 4; j++) acc2[i][j] = 0ull;

    const unsigned long long* Arow = (const unsigned long long*)(As2 + tb * 8);
    const unsigned long long* Brow = (const unsigned long long*)(Wp2 + to * 4);

#pragma unroll 4
    for (int kp = 0; kp < 32; kp++) {
        ulonglong2 A0 = *(const ulonglong2*)(Arow + kp * 128 + 0);
        ulonglong2 A1 = *(const ulonglong2*)(Arow + kp * 128 + 2);
        ulonglong2 A2 = *(const ulonglong2*)(Arow + kp * 128 + 4);
        ulonglong2 A3 = *(const ulonglong2*)(Arow + kp * 128 + 6);
        ulonglong2 B0 = *(const ulonglong2*)(Brow + kp * WROW + 0);
        ulonglong2 B1 = *(const ulonglong2*)(Brow + kp * WROW + 2);
        unsigned long long a2[8] = {A0.x, A0.y, A1.x, A1.y, A2.x, A2.y, A3.x, A3.y};
        unsigned long long b2[4] = {B0.x, B0.y, B1.x, B1.y};
#pragma unroll
        for (int i = 0; i < 8; i++)
#pragma unroll
            for (int j = 0; j < 4; j++) {
                asm("fma.rn.f32x2 %0, %1, %2, %0;"
                    : "+l"(acc2[i][j]) : "l"(a2[i]), "l"(b2[j]));
            }
    }

    // Epilogue: thread's 4 o's consecutive (uj 0..3) -> one STG.128 per b-row
    const int i4 = (p >> 4) << 2, j4 = (p & 15) << 2;
    int o0 = bn * 64 + to * 4;
    int t  = o0 >> 4;
    int ui = (o0 >> 2) & 3;
    int coloff = t * 4096 + (i4 + ui) * 64 + j4;
    float4 bv = *(const float4*)&bias_s[to * 4];
#pragma unroll
    for (int i = 0; i < 8; i++) {
        int row = bm * 128 + tb * 8 + i;
        float2 c0 = unpackf2(acc2[i][0]);
        float2 c1 = unpackf2(acc2[i][1]);
        float2 c2 = unpackf2(acc2[i][2]);
        float2 c3 = unpackf2(acc2[i][3]);
        float4 v = make_float4(c0.x + c0.y + bv.x, c1.x + c1.y + bv.y,
                               c2.x + c2.y + bv.z, c3.x + c3.y + bv.w);
        *(float4*)(out + (size_t)row * 262144 + coloff) = v;
    }
}

extern "C" void kernel_launch(void* const* d_in, const int* in_sizes, int n_in,
                              void* d_out, int out_size) {
    const float* x = (const float*)d_in[0];   // (256, 64, 16, 16)
    const float* W = (const float*)d_in[1];   // (256, 1024, 64)
    const float* b = (const float*)d_in[2];   // (256, 1024)
    float* out = (float*)d_out;               // (256, 64, 64, 64)
    (void)in_sizes; (void)n_in; (void)out_size;

    cudaFuncSetAttribute(gemm_kernel, cudaFuncAttributeMaxDynamicSharedMemorySize, SMEM_BYTES);

    transpose_pair<<<dim3(8, 8, 4), dim3(32, 8)>>>(x);
    gemm_kernel<<<dim3(16, 2, 256), 256, SMEM_BYTES>>>(W, b, out);
}